// round 1
// baseline (speedup 1.0000x reference)
#include <cuda_runtime.h>
#include <math.h>

#define CCH   64
#define NPIX  (512*512)
#define TP    128          // stats tile pixels
#define AP    80           // stats smem pitch (floats): 80%32=16 -> 2-way, 16B aligned
#define GX    148          // stats grid.x
#define NT    (NPIX/TP)    // 2048 tiles
#define PITCH 68           // 64x64 matrix smem pitch (floats), 16B aligned
#define TPA   256          // apply tile pixels
#define APA   264          // apply smem pitch
#define NS_ITERS 9

// ---------------- global scratch (static __device__, no allocations) ----------------
__device__ float g_partC[GX*2*4*4096];
__device__ float g_partS[GX*2*4*4096];
__device__ float g_S1c[8*64];
__device__ float g_S1s[8*64];
__device__ float g_cntc[8];
__device__ float g_cnts[8];
__device__ float g_S2c[8*4096];
__device__ float g_S2s[8*4096];
__device__ float g_Wh[8*4096];   // cov_c^{-1/2}
__device__ float g_Co[8*4096];   // cov_s^{+1/2}
__device__ float g_Tt[8*4096];   // T transposed: g_Tt[l][k][c] = T[c][k]
__device__ float g_bv[8*64];     // b = mu_s - T mu_c (0 if invalid)

// ---------------- zero small accumulators ----------------
__global__ void zero_kernel() {
    int i = blockIdx.x * blockDim.x + threadIdx.x;
    if (i < 8*64) { g_S1c[i] = 0.f; g_S1s[i] = 0.f; }
    if (i < 8)    { g_cntc[i] = 0.f; g_cnts[i] = 0.f; }
}

// ---------------- stats: per-label counts, sums, raw second moments ----------------
// grid (GX, 2): blockIdx.y picks labels [4*gy, 4*gy+4). Each block writes its own
// partial Gram slab (no atomics on the heavy path).
__global__ void stats_kernel(const float* __restrict__ X,
                             const int*   __restrict__ segp,
                             int side)
{
    extern __shared__ float As[];            // TP * AP floats
    __shared__ int sh_lab[TP];
    __shared__ int sh_perm[TP];
    __shared__ int sh_hist[8];
    __shared__ int sh_off[8];
    __shared__ int sh_seg[9];

    const int tid = threadIdx.x;
    const int gy  = blockIdx.y;
    const int l0  = gy * 4;
    const int ti  = tid >> 4, tj = tid & 15;

    float acc[4][16];
#pragma unroll
    for (int a = 0; a < 4; a++)
#pragma unroll
        for (int b = 0; b < 16; b++) acc[a][b] = 0.f;
    float s1[4] = {0.f,0.f,0.f,0.f};
    float cl[4] = {0.f,0.f,0.f,0.f};

    for (int tile = blockIdx.x; tile < NT; tile += GX) {
        const int base = tile * TP;
        if (tid < 8) sh_hist[tid] = 0;
        __syncthreads();
        if (tid < TP) {
            int lb = segp[base + tid];
            lb = lb < 0 ? 0 : (lb > 7 ? 7 : lb);
            sh_lab[tid] = lb;
            atomicAdd(&sh_hist[lb], 1);
        }
        __syncthreads();
        if (tid == 0) {
            int a = 0;
#pragma unroll
            for (int i = 0; i < 8; i++) { sh_seg[i] = a; sh_off[i] = a; a += sh_hist[i]; }
            sh_seg[8] = a;
        }
        __syncthreads();
        if (tid < TP) {
            int pos = atomicAdd(&sh_off[sh_lab[tid]], 1);
            sh_perm[pos] = tid;
        }
        // load tile: As[p][c], global coalesced over p
        for (int e = tid; e < TP*CCH; e += 256) {
            int c = e >> 7, p = e & 127;
            As[p*AP + c] = X[c*NPIX + base + p];
        }
        __syncthreads();

#pragma unroll
        for (int ll = 0; ll < 4; ll++) {
            const int s = sh_seg[l0+ll], e = sh_seg[l0+ll+1];
            if (tid == 0) cl[ll] += (float)(e - s);
            for (int k = s; k < e; k++) {
                const int kk = sh_perm[k];
                const float4 av = *(const float4*)&As[kk*AP + 4*ti];
                const float4 bv = *(const float4*)&As[kk*AP + 4*tj];
                acc[ll][0]  += av.x*bv.x; acc[ll][1]  += av.x*bv.y;
                acc[ll][2]  += av.x*bv.z; acc[ll][3]  += av.x*bv.w;
                acc[ll][4]  += av.y*bv.x; acc[ll][5]  += av.y*bv.y;
                acc[ll][6]  += av.y*bv.z; acc[ll][7]  += av.y*bv.w;
                acc[ll][8]  += av.z*bv.x; acc[ll][9]  += av.z*bv.y;
                acc[ll][10] += av.z*bv.z; acc[ll][11] += av.z*bv.w;
                acc[ll][12] += av.w*bv.x; acc[ll][13] += av.w*bv.y;
                acc[ll][14] += av.w*bv.z; acc[ll][15] += av.w*bv.w;
                if (tid < 64) s1[ll] += As[kk*AP + tid];
            }
        }
        __syncthreads();
    }

    // flush partial Grams (non-atomic, own slab)
    float* part = (side ? g_partS : g_partC) + (size_t)((gy*GX + blockIdx.x)*4) * 4096;
#pragma unroll
    for (int ll = 0; ll < 4; ll++)
#pragma unroll
        for (int a = 0; a < 4; a++) {
            float4 v = make_float4(acc[ll][a*4+0], acc[ll][a*4+1],
                                   acc[ll][a*4+2], acc[ll][a*4+3]);
            *(float4*)&part[ll*4096 + (4*ti + a)*64 + 4*tj] = v;
        }
    float* S1  = side ? g_S1s : g_S1c;
    float* cnt = side ? g_cnts : g_cntc;
    if (tid < 64) {
#pragma unroll
        for (int ll = 0; ll < 4; ll++) atomicAdd(&S1[(l0+ll)*64 + tid], s1[ll]);
    }
    if (tid == 0) {
#pragma unroll
        for (int ll = 0; ll < 4; ll++) atomicAdd(&cnt[l0+ll], cl[ll]);
    }
}

// ---------------- reduce partial Grams -> S2 ----------------
__global__ void reduce_kernel(int side) {
    int idx = blockIdx.x * blockDim.x + threadIdx.x;   // 8*4096 entries
    if (idx >= 8*4096) return;
    const int l = idx >> 12, e = idx & 4095;
    const int gy = l >> 2, ll = l & 3;
    const float* part = (side ? g_partS : g_partC);
    const float* p = part + (size_t)(gy*GX)*4*4096 + ll*4096 + e;
    float s = 0.f;
    for (int b = 0; b < GX; b++) s += p[(size_t)b*4*4096];
    float* S2 = side ? g_S2s : g_S2c;
    S2[idx] = s;
}

// ---------------- 64x64 matmul helper (smem, pitch PITCH) ----------------
__device__ __forceinline__ void mm64(const float* __restrict__ A,
                                     const float* __restrict__ B,
                                     float* acc, int ti, int tj)
{
#pragma unroll 8
    for (int k = 0; k < 64; k++) {
        float a0 = A[(4*ti+0)*PITCH + k];
        float a1 = A[(4*ti+1)*PITCH + k];
        float a2 = A[(4*ti+2)*PITCH + k];
        float a3 = A[(4*ti+3)*PITCH + k];
        float4 b = *(const float4*)&B[k*PITCH + 4*tj];
        acc[0]  += a0*b.x; acc[1]  += a0*b.y; acc[2]  += a0*b.z; acc[3]  += a0*b.w;
        acc[4]  += a1*b.x; acc[5]  += a1*b.y; acc[6]  += a1*b.z; acc[7]  += a1*b.w;
        acc[8]  += a2*b.x; acc[9]  += a2*b.y; acc[10] += a2*b.z; acc[11] += a2*b.w;
        acc[12] += a3*b.x; acc[13] += a3*b.y; acc[14] += a3*b.z; acc[15] += a3*b.w;
    }
}

// ---------------- finalize: cov build + Newton-Schulz sqrt / invsqrt ----------------
// grid (8, 2): side 0 -> content (Wh = cov^{-1/2}, cov has +I), side 1 -> style (Co = cov^{1/2})
__global__ void finalize_ns() {
    const int l = blockIdx.x, side = blockIdx.y;
    extern __shared__ float sm[];
    float* Y  = sm;
    float* Z  = Y  + 64*PITCH;
    float* M  = Z  + 64*PITCH;
    float* Y2 = M  + 64*PITCH;
    float* Z2 = Y2 + 64*PITCH;
    __shared__ float sh_red[64];
    __shared__ float sh_c;
    const int tid = threadIdx.x;
    const float* S2 = side ? g_S2s : g_S2c;
    const float* S1 = side ? g_S1s : g_S1c;
    const float  n  = side ? g_cnts[l] : g_cntc[l];
    float* outM = side ? g_Co : g_Wh;

    if (n < 10.5f) {   // label too small on this side -> invalid anyway; write I
        for (int e = tid; e < 4096; e += 256) {
            int i = e >> 6, j = e & 63;
            outM[l*4096 + e] = (i == j) ? 1.f : 0.f;
        }
        return;
    }
    const float inv_n = 1.f / n;
    const float nm1 = n - 1.f;
    const float invdiv = 1.f / ((nm1 == 0.f) ? 1e-5f : nm1);
    for (int e = tid; e < 4096; e += 256) {
        int i = e >> 6, j = e & 63;
        float mui = S1[l*64 + i] * inv_n;
        float muj = S1[l*64 + j] * inv_n;
        float v = (S2[l*4096 + e] - n*mui*muj) * invdiv;
        if (side == 0 && i == j) v += 1.f;
        Y[i*PITCH + j] = v;
        Z[i*PITCH + j] = (i == j) ? 1.f : 0.f;
    }
    __syncthreads();
    if (tid < 64) {
        float rs = 0.f;
        for (int j = 0; j < 64; j++) rs += fabsf(Y[tid*PITCH + j]);
        sh_red[tid] = rs;
    }
    __syncthreads();
    if (tid == 0) {
        float m = 1e-30f;
        for (int i = 0; i < 64; i++) m = fmaxf(m, sh_red[i]);
        sh_c = m;
    }
    __syncthreads();
    const float c = sh_c, invc = 1.f / c;
    for (int e = tid; e < 4096; e += 256) {
        int i = e >> 6, j = e & 63;
        Y[i*PITCH + j] *= invc;
    }
    __syncthreads();

    const int ti = tid >> 4, tj = tid & 15;
    float *yA = Y, *zA = Z, *yB = Y2, *zB = Z2;
    for (int it = 0; it < NS_ITERS; it++) {
        float accM[16];
#pragma unroll
        for (int q = 0; q < 16; q++) accM[q] = 0.f;
        mm64(zA, yA, accM, ti, tj);
#pragma unroll
        for (int a = 0; a < 4; a++) {
            float4 v = make_float4(accM[a*4+0], accM[a*4+1], accM[a*4+2], accM[a*4+3]);
            *(float4*)&M[(4*ti + a)*PITCH + 4*tj] = v;
        }
        __syncthreads();
        float accY[16], accZ[16];
#pragma unroll
        for (int q = 0; q < 16; q++) { accY[q] = 0.f; accZ[q] = 0.f; }
        mm64(yA, M, accY, ti, tj);
        mm64(M, zA, accZ, ti, tj);
#pragma unroll
        for (int a = 0; a < 4; a++)
#pragma unroll
            for (int b = 0; b < 4; b++) {
                int r = 4*ti + a, cc = 4*tj + b;
                yB[r*PITCH + cc] = 1.5f*yA[r*PITCH + cc] - 0.5f*accY[a*4+b];
                zB[r*PITCH + cc] = 1.5f*zA[r*PITCH + cc] - 0.5f*accZ[a*4+b];
            }
        __syncthreads();
        float* t;
        t = yA; yA = yB; yB = t;
        t = zA; zA = zB; zB = t;
    }
    const float scale = side ? sqrtf(c) : rsqrtf(c);
    const float* R = side ? yA : zA;
    for (int e = tid; e < 4096; e += 256) {
        int i = e >> 6, j = e & 63;
        outM[l*4096 + e] = R[i*PITCH + j] * scale;
    }
}

// ---------------- combine: T = Co@Wh (transposed store), b = mu_s - T mu_c ----------------
__global__ void combine_kernel(const int* nlab_ptr) {
    const int l = blockIdx.x, tid = threadIdx.x;
    extern __shared__ float sm[];
    float* sCo = sm;                 // 64*PITCH
    float* sWh = sm + 64*PITCH;      // 64*PITCH
    __shared__ float sh_b[64];
    __shared__ float sh_muc[64], sh_mus[64];

    int nlab = 8;
    if (nlab_ptr) nlab = *nlab_ptr;
    const float nc = g_cntc[l], ns = g_cnts[l];
    const bool valid = (l < nlab) && (nc > 10.f) && (ns > 10.f) &&
                       (nc < 100.f*ns) && (ns < 100.f*nc);

    for (int e = tid; e < 4096; e += 256) {
        int i = e >> 6, j = e & 63;
        sCo[i*PITCH + j] = g_Co[l*4096 + e];
        sWh[i*PITCH + j] = g_Wh[l*4096 + e];
    }
    if (tid < 64) {
        sh_muc[tid] = g_S1c[l*64 + tid] / fmaxf(nc, 1.f);
        sh_mus[tid] = g_S1s[l*64 + tid] / fmaxf(ns, 1.f);
        sh_b[tid] = 0.f;
    }
    __syncthreads();

    const int ti = tid >> 4, tj = tid & 15;
    float acc[16];
#pragma unroll
    for (int q = 0; q < 16; q++) acc[q] = 0.f;
    mm64(sCo, sWh, acc, ti, tj);

    float bpart[4] = {0.f,0.f,0.f,0.f};
#pragma unroll
    for (int a = 0; a < 4; a++)
#pragma unroll
        for (int b = 0; b < 4; b++) {
            int i = 4*ti + a, j = 4*tj + b;
            float tv = valid ? acc[a*4+b] : ((i == j) ? 1.f : 0.f);
            g_Tt[l*4096 + j*64 + i] = tv;     // transposed store [k][c]
            bpart[a] += acc[a*4+b] * sh_muc[j];
        }
#pragma unroll
    for (int a = 0; a < 4; a++) atomicAdd(&sh_b[4*ti + a], bpart[a]);
    __syncthreads();
    if (tid < 64) g_bv[l*64 + tid] = valid ? (sh_mus[tid] - sh_b[tid]) : 0.f;
}

// ---------------- apply: out[:,p] = T_{seg(p)} x_p + b ----------------
__global__ void __launch_bounds__(256)
apply_kernel(const float* __restrict__ X,
             const int*   __restrict__ segp,
             float*       __restrict__ out)
{
    extern __shared__ float sm[];
    float* As = sm;                    // 64 * APA
    float* Ts = sm + 64*APA;           // 64 * PITCH
    __shared__ float sh_bv[64];
    __shared__ int sh_lab[TPA], sh_perm[TPA], sh_spos[TPA];
    __shared__ int sh_hist[8], sh_off[8], sh_seg[9];

    const int tid = threadIdx.x;
    const int base = blockIdx.x * TPA;

    if (tid < 8) sh_hist[tid] = 0;
    __syncthreads();
    {
        int lb = segp[base + tid];
        lb = lb < 0 ? 0 : (lb > 7 ? 7 : lb);
        sh_lab[tid] = lb;
        atomicAdd(&sh_hist[lb], 1);
    }
    __syncthreads();
    if (tid == 0) {
        int a = 0;
#pragma unroll
        for (int i = 0; i < 8; i++) { sh_seg[i] = a; sh_off[i] = a; a += sh_hist[i]; }
        sh_seg[8] = a;
    }
    __syncthreads();
    {
        int pos = atomicAdd(&sh_off[sh_lab[tid]], 1);
        sh_spos[tid] = pos;
        sh_perm[pos] = tid;
    }
    __syncthreads();
    // load features into label-sorted columns
    for (int e = tid; e < CCH*TPA; e += 256) {
        int c = e >> 8, p = e & 255;
        As[c*APA + sh_spos[p]] = X[c*NPIX + base + p];
    }
    __syncthreads();

    const int tpg = tid >> 4, tr = tid & 15;
    for (int l = 0; l < 8; l++) {
        const int s = sh_seg[l], e = sh_seg[l+1];
        if (s == e) continue;                   // uniform across block
        for (int idx = tid; idx < 4096; idx += 256)
            Ts[(idx >> 6)*PITCH + (idx & 63)] = g_Tt[l*4096 + idx];
        if (tid < 64) sh_bv[tid] = g_bv[l*64 + tid];
        __syncthreads();

#pragma unroll
        for (int pass = 0; pass < 2; pass++) {
            const int p0 = s + pass*128 + 8*tpg;
            if (p0 < e) {
                int m = e - p0; if (m > 8) m = 8;
                float acc[4][8];
#pragma unroll
                for (int r = 0; r < 4; r++)
#pragma unroll
                    for (int u = 0; u < 8; u++) acc[r][u] = 0.f;
#pragma unroll 4
                for (int k = 0; k < 64; k++) {
                    float4 tv = *(const float4*)&Ts[k*PITCH + 4*tr];
                    float x[8];
#pragma unroll
                    for (int u = 0; u < 8; u++) x[u] = As[k*APA + p0 + u];
#pragma unroll
                    for (int u = 0; u < 8; u++) {
                        acc[0][u] += tv.x * x[u];
                        acc[1][u] += tv.y * x[u];
                        acc[2][u] += tv.z * x[u];
                        acc[3][u] += tv.w * x[u];
                    }
                }
#pragma unroll
                for (int r = 0; r < 4; r++) {
                    const int ch = 4*tr + r;
                    const float bb = sh_bv[ch];
                    for (int u = 0; u < m; u++) {
                        int pix = sh_perm[p0 + u];
                        out[ch*NPIX + base + pix] = acc[r][u] + bb;
                    }
                }
            }
        }
        __syncthreads();
    }
}

// ---------------- launch ----------------
extern "C" void kernel_launch(void* const* d_in, const int* in_sizes, int n_in,
                              void* d_out, int out_size)
{
    const float* Xc   = (const float*)d_in[0];
    const float* Xs   = (const float*)d_in[1];
    const int*   segc = (const int*)d_in[2];
    const int*   segs = (const int*)d_in[3];
    const int*   nlab = (n_in >= 5) ? (const int*)d_in[4] : nullptr;
    float* out = (float*)d_out;

    const int smem_stats = TP*AP*4;                 // 40960
    const int smem_ns    = 5*64*PITCH*4;            // 87040
    const int smem_comb  = 2*64*PITCH*4;            // 34816
    const int smem_apply = (64*APA + 64*PITCH)*4;   // 84992

    cudaFuncSetAttribute(finalize_ns,  cudaFuncAttributeMaxDynamicSharedMemorySize, smem_ns);
    cudaFuncSetAttribute(apply_kernel, cudaFuncAttributeMaxDynamicSharedMemorySize, smem_apply);

    zero_kernel<<<2, 256>>>();
    stats_kernel<<<dim3(GX, 2), 256, smem_stats>>>(Xc, segc, 0);
    stats_kernel<<<dim3(GX, 2), 256, smem_stats>>>(Xs, segs, 1);
    reduce_kernel<<<128, 256>>>(0);
    reduce_kernel<<<128, 256>>>(1);
    finalize_ns<<<dim3(8, 2), 256, smem_ns>>>();
    combine_kernel<<<8, 256, smem_comb>>>(nlab);
    apply_kernel<<<NPIX/TPA, 256, smem_apply>>>(Xc, segc, out);
}

// round 2
// speedup vs baseline: 1.1130x; 1.1130x over previous
#include <cuda_runtime.h>
#include <math.h>

#define CCH   64
#define NPIX  (512*512)
#define TP    256          // stats tile pixels
#define GX    148          // stats grid.x
#define NT    (NPIX/TP)    // 1024 tiles
#define PITCH 68           // 64x64 matrix smem pitch (floats), 16B aligned
#define TPA   256          // apply tile pixels
#define APA   288          // apply smem pitch (floats)
#define TSP   72           // apply T smem pitch
#define NS_ITERS 9

// ---------------- global scratch (static __device__, no allocations) ----------------
__device__ float g_partC[GX*2*4*4096];
__device__ float g_partS[GX*2*4*4096];
__device__ float g_S1c[8*64];
__device__ float g_S1s[8*64];
__device__ float g_cntc[8];
__device__ float g_cnts[8];
__device__ float g_S2c[8*4096];
__device__ float g_S2s[8*4096];
__device__ float g_Wh[8*4096];   // cov_c^{-1/2}
__device__ float g_Co[8*4096];   // cov_s^{+1/2}
__device__ float g_Tt[8*4096];   // T transposed: g_Tt[l][k][c] = T[c][k]
__device__ float g_bv[8*64];     // b = mu_s - T mu_c (0 if invalid)

// swizzled pixel-major address: row p of 64 floats, float4-granular XOR swizzle
__device__ __forceinline__ int swaddr(int p, int c) {
    return p*64 + ((((c >> 2) ^ (p & 15)) << 2) | (c & 3));
}

// ---------------- zero small accumulators ----------------
__global__ void zero_kernel() {
    int i = blockIdx.x * blockDim.x + threadIdx.x;
    if (i < 8*64) { g_S1c[i] = 0.f; g_S1s[i] = 0.f; }
    if (i < 8)    { g_cntc[i] = 0.f; g_cnts[i] = 0.f; }
}

#define FMA16(ACC, AV, BV) do { \
    ACC[0]  += AV.x*BV.x; ACC[1]  += AV.x*BV.y; ACC[2]  += AV.x*BV.z; ACC[3]  += AV.x*BV.w; \
    ACC[4]  += AV.y*BV.x; ACC[5]  += AV.y*BV.y; ACC[6]  += AV.y*BV.z; ACC[7]  += AV.y*BV.w; \
    ACC[8]  += AV.z*BV.x; ACC[9]  += AV.z*BV.y; ACC[10] += AV.z*BV.z; ACC[11] += AV.z*BV.w; \
    ACC[12] += AV.w*BV.x; ACC[13] += AV.w*BV.y; ACC[14] += AV.w*BV.z; ACC[15] += AV.w*BV.w; \
} while (0)

// ---------------- stats: per-label counts, sums, raw second moments ----------------
// grid (GX, 2, 2): y = label-group (4 labels each), z = side (0 content, 1 style)
__global__ void __launch_bounds__(256, 2)
stats_kernel(const float* __restrict__ Xc, const float* __restrict__ Xs,
             const int* __restrict__ segc, const int* __restrict__ segs)
{
    extern __shared__ float As[];            // TP * 64 floats (swizzled)
    const float4* As4 = (const float4*)As;
    __shared__ int sh_perm[TP];
    __shared__ int sh_hist[8];
    __shared__ int sh_off[8];
    __shared__ int sh_seg[9];

    const int tid = threadIdx.x;
    const int gy  = blockIdx.y;
    const int side = blockIdx.z;
    const float* X   = side ? Xs : Xc;
    const int*  segp = side ? segs : segc;
    const int l0  = gy * 4;
    const int ti  = tid >> 4, tj = tid & 15;

    float acc[4][16];
#pragma unroll
    for (int a = 0; a < 4; a++)
#pragma unroll
        for (int b = 0; b < 16; b++) acc[a][b] = 0.f;
    float s1[4] = {0.f,0.f,0.f,0.f};
    float cl[4] = {0.f,0.f,0.f,0.f};

    for (int tile = blockIdx.x; tile < NT; tile += GX) {
        const int base = tile * TP;
        if (tid < 8) sh_hist[tid] = 0;
        __syncthreads();
        int lb = segp[base + tid];
        lb = lb < 0 ? 0 : (lb > 7 ? 7 : lb);
        atomicAdd(&sh_hist[lb], 1);
        __syncthreads();
        if (tid == 0) {
            int a = 0;
#pragma unroll
            for (int i = 0; i < 8; i++) { sh_seg[i] = a; sh_off[i] = a; a += sh_hist[i]; }
            sh_seg[8] = a;
        }
        __syncthreads();
        {
            int pos = atomicAdd(&sh_off[lb], 1);
            sh_perm[pos] = tid;
        }
        // load tile into swizzled pixel-major smem; global coalesced, STS ~2-way
        for (int e = tid; e < TP*CCH; e += 256) {
            int c = e >> 8, p = e & 255;
            As[swaddr(p, c)] = X[(size_t)c*NPIX + base + p];
        }
        __syncthreads();

#pragma unroll
        for (int ll = 0; ll < 4; ll++) {
            const int s = sh_seg[l0+ll], e = sh_seg[l0+ll+1];
            if (tid == 0) cl[ll] += (float)(e - s);
            int k = s;
            for (; k + 2 <= e; k += 2) {
                const int k0 = sh_perm[k], k1 = sh_perm[k+1];
                const float4 a0 = As4[k0*16 + (ti ^ (k0 & 15))];
                const float4 b0 = As4[k0*16 + (tj ^ (k0 & 15))];
                const float4 a1 = As4[k1*16 + (ti ^ (k1 & 15))];
                const float4 b1 = As4[k1*16 + (tj ^ (k1 & 15))];
                FMA16(acc[ll], a0, b0);
                FMA16(acc[ll], a1, b1);
                if (tid < 64) s1[ll] += As[swaddr(k0, tid)] + As[swaddr(k1, tid)];
            }
            if (k < e) {
                const int k0 = sh_perm[k];
                const float4 a0 = As4[k0*16 + (ti ^ (k0 & 15))];
                const float4 b0 = As4[k0*16 + (tj ^ (k0 & 15))];
                FMA16(acc[ll], a0, b0);
                if (tid < 64) s1[ll] += As[swaddr(k0, tid)];
            }
        }
        __syncthreads();
    }

    // flush partial Grams (non-atomic, own slab)
    float* part = (side ? g_partS : g_partC) + (size_t)((gy*GX + blockIdx.x)*4) * 4096;
#pragma unroll
    for (int ll = 0; ll < 4; ll++)
#pragma unroll
        for (int a = 0; a < 4; a++) {
            float4 v = make_float4(acc[ll][a*4+0], acc[ll][a*4+1],
                                   acc[ll][a*4+2], acc[ll][a*4+3]);
            *(float4*)&part[ll*4096 + (4*ti + a)*64 + 4*tj] = v;
        }
    float* S1  = side ? g_S1s : g_S1c;
    float* cnt = side ? g_cnts : g_cntc;
    if (tid < 64) {
#pragma unroll
        for (int ll = 0; ll < 4; ll++) atomicAdd(&S1[(l0+ll)*64 + tid], s1[ll]);
    }
    if (tid == 0) {
#pragma unroll
        for (int ll = 0; ll < 4; ll++) atomicAdd(&cnt[l0+ll], cl[ll]);
    }
}

// ---------------- reduce partial Grams -> S2 (both sides in one launch) ----------------
__global__ void reduce_kernel() {
    int idx = blockIdx.x * blockDim.x + threadIdx.x;   // 0 .. 2*8*4096-1
    const int side = idx >> 15;
    const int rest = idx & 32767;
    const int l = rest >> 12;
    const int gy = l >> 2, ll = l & 3;
    const float* part = (side ? g_partS : g_partC);
    const float* p = part + ((size_t)(gy*GX)*4 + ll)*4096 + (rest & 4095);
    float s = 0.f;
#pragma unroll 4
    for (int b = 0; b < GX; b++) s += p[(size_t)b*4*4096];
    (side ? g_S2s : g_S2c)[rest] = s;
}

// ---------------- 64x64 matmul helper (smem, pitch PITCH), float4 loads ----------------
__device__ __forceinline__ void mm64v(const float* __restrict__ A,
                                      const float* __restrict__ B,
                                      float (&acc)[16], int ti, int tj)
{
#pragma unroll 4
    for (int k0 = 0; k0 < 64; k0 += 4) {
        const float4 a0 = *(const float4*)&A[(4*ti+0)*PITCH + k0];
        const float4 a1 = *(const float4*)&A[(4*ti+1)*PITCH + k0];
        const float4 a2 = *(const float4*)&A[(4*ti+2)*PITCH + k0];
        const float4 a3 = *(const float4*)&A[(4*ti+3)*PITCH + k0];
        const float4 b0 = *(const float4*)&B[(k0+0)*PITCH + 4*tj];
        const float4 b1 = *(const float4*)&B[(k0+1)*PITCH + 4*tj];
        const float4 b2 = *(const float4*)&B[(k0+2)*PITCH + 4*tj];
        const float4 b3 = *(const float4*)&B[(k0+3)*PITCH + 4*tj];
        acc[0]+=a0.x*b0.x; acc[1]+=a0.x*b0.y; acc[2]+=a0.x*b0.z; acc[3]+=a0.x*b0.w;
        acc[4]+=a1.x*b0.x; acc[5]+=a1.x*b0.y; acc[6]+=a1.x*b0.z; acc[7]+=a1.x*b0.w;
        acc[8]+=a2.x*b0.x; acc[9]+=a2.x*b0.y; acc[10]+=a2.x*b0.z; acc[11]+=a2.x*b0.w;
        acc[12]+=a3.x*b0.x; acc[13]+=a3.x*b0.y; acc[14]+=a3.x*b0.z; acc[15]+=a3.x*b0.w;
        acc[0]+=a0.y*b1.x; acc[1]+=a0.y*b1.y; acc[2]+=a0.y*b1.z; acc[3]+=a0.y*b1.w;
        acc[4]+=a1.y*b1.x; acc[5]+=a1.y*b1.y; acc[6]+=a1.y*b1.z; acc[7]+=a1.y*b1.w;
        acc[8]+=a2.y*b1.x; acc[9]+=a2.y*b1.y; acc[10]+=a2.y*b1.z; acc[11]+=a2.y*b1.w;
        acc[12]+=a3.y*b1.x; acc[13]+=a3.y*b1.y; acc[14]+=a3.y*b1.z; acc[15]+=a3.y*b1.w;
        acc[0]+=a0.z*b2.x; acc[1]+=a0.z*b2.y; acc[2]+=a0.z*b2.z; acc[3]+=a0.z*b2.w;
        acc[4]+=a1.z*b2.x; acc[5]+=a1.z*b2.y; acc[6]+=a1.z*b2.z; acc[7]+=a1.z*b2.w;
        acc[8]+=a2.z*b2.x; acc[9]+=a2.z*b2.y; acc[10]+=a2.z*b2.z; acc[11]+=a2.z*b2.w;
        acc[12]+=a3.z*b2.x; acc[13]+=a3.z*b2.y; acc[14]+=a3.z*b2.z; acc[15]+=a3.z*b2.w;
        acc[0]+=a0.w*b3.x; acc[1]+=a0.w*b3.y; acc[2]+=a0.w*b3.z; acc[3]+=a0.w*b3.w;
        acc[4]+=a1.w*b3.x; acc[5]+=a1.w*b3.y; acc[6]+=a1.w*b3.z; acc[7]+=a1.w*b3.w;
        acc[8]+=a2.w*b3.x; acc[9]+=a2.w*b3.y; acc[10]+=a2.w*b3.z; acc[11]+=a2.w*b3.w;
        acc[12]+=a3.w*b3.x; acc[13]+=a3.w*b3.y; acc[14]+=a3.w*b3.z; acc[15]+=a3.w*b3.w;
    }
}

// ---------------- finalize: cov build + Newton-Schulz sqrt / invsqrt ----------------
__global__ void __launch_bounds__(256) finalize_ns() {
    const int l = blockIdx.x, side = blockIdx.y;
    extern __shared__ float sm[];
    float* Y  = sm;
    float* Z  = Y  + 64*PITCH;
    float* M  = Z  + 64*PITCH;
    float* Y2 = M  + 64*PITCH;
    float* Z2 = Y2 + 64*PITCH;
    __shared__ float sh_red[64];
    __shared__ float sh_c;
    const int tid = threadIdx.x;
    const float* S2 = side ? g_S2s : g_S2c;
    const float* S1 = side ? g_S1s : g_S1c;
    const float  n  = side ? g_cnts[l] : g_cntc[l];
    float* outM = side ? g_Co : g_Wh;

    if (n < 10.5f) {   // invalid anyway; write I
        for (int e = tid; e < 4096; e += 256) {
            int i = e >> 6, j = e & 63;
            outM[l*4096 + e] = (i == j) ? 1.f : 0.f;
        }
        return;
    }
    const float inv_n = 1.f / n;
    const float nm1 = n - 1.f;
    const float invdiv = 1.f / ((nm1 == 0.f) ? 1e-5f : nm1);
    for (int e = tid; e < 4096; e += 256) {
        int i = e >> 6, j = e & 63;
        float mui = S1[l*64 + i] * inv_n;
        float muj = S1[l*64 + j] * inv_n;
        float v = (S2[l*4096 + e] - n*mui*muj) * invdiv;
        if (side == 0 && i == j) v += 1.f;
        Y[i*PITCH + j] = v;
        Z[i*PITCH + j] = (i == j) ? 1.f : 0.f;
    }
    __syncthreads();
    if (tid < 64) {
        float rs = 0.f;
        for (int j = 0; j < 64; j++) rs += fabsf(Y[tid*PITCH + j]);
        sh_red[tid] = rs;
    }
    __syncthreads();
    if (tid == 0) {
        float m = 1e-30f;
        for (int i = 0; i < 64; i++) m = fmaxf(m, sh_red[i]);
        sh_c = m;
    }
    __syncthreads();
    const float c = sh_c, invc = 1.f / c;
    for (int e = tid; e < 4096; e += 256) {
        int i = e >> 6, j = e & 63;
        Y[i*PITCH + j] *= invc;
    }
    __syncthreads();

    const int ti = tid >> 4, tj = tid & 15;
    float *yA = Y, *zA = Z, *yB = Y2, *zB = Z2;
    for (int it = 0; it < NS_ITERS; it++) {
        float accM[16];
#pragma unroll
        for (int q = 0; q < 16; q++) accM[q] = 0.f;
        mm64v(zA, yA, accM, ti, tj);
#pragma unroll
        for (int a = 0; a < 4; a++) {
            float4 v = make_float4(accM[a*4+0], accM[a*4+1], accM[a*4+2], accM[a*4+3]);
            *(float4*)&M[(4*ti + a)*PITCH + 4*tj] = v;
        }
        __syncthreads();
        float accY[16], accZ[16];
#pragma unroll
        for (int q = 0; q < 16; q++) { accY[q] = 0.f; accZ[q] = 0.f; }
        mm64v(yA, M, accY, ti, tj);
        mm64v(M, zA, accZ, ti, tj);
#pragma unroll
        for (int a = 0; a < 4; a++)
#pragma unroll
            for (int b = 0; b < 4; b++) {
                int r = 4*ti + a, cc = 4*tj + b;
                yB[r*PITCH + cc] = 1.5f*yA[r*PITCH + cc] - 0.5f*accY[a*4+b];
                zB[r*PITCH + cc] = 1.5f*zA[r*PITCH + cc] - 0.5f*accZ[a*4+b];
            }
        __syncthreads();
        float* t;
        t = yA; yA = yB; yB = t;
        t = zA; zA = zB; zB = t;
    }
    const float scale = side ? sqrtf(c) : rsqrtf(c);
    const float* R = side ? yA : zA;
    for (int e = tid; e < 4096; e += 256) {
        int i = e >> 6, j = e & 63;
        outM[l*4096 + e] = R[i*PITCH + j] * scale;
    }
}

// ---------------- combine: T = Co@Wh (transposed store), b = mu_s - T mu_c ----------------
__global__ void combine_kernel(const int* nlab_ptr) {
    const int l = blockIdx.x, tid = threadIdx.x;
    extern __shared__ float sm[];
    float* sCo = sm;                 // 64*PITCH
    float* sWh = sm + 64*PITCH;      // 64*PITCH
    __shared__ float sh_b[64];
    __shared__ float sh_muc[64], sh_mus[64];

    int nlab = 8;
    if (nlab_ptr) nlab = *nlab_ptr;
    const float nc = g_cntc[l], ns = g_cnts[l];
    const bool valid = (l < nlab) && (nc > 10.f) && (ns > 10.f) &&
                       (nc < 100.f*ns) && (ns < 100.f*nc);

    for (int e = tid; e < 4096; e += 256) {
        int i = e >> 6, j = e & 63;
        sCo[i*PITCH + j] = g_Co[l*4096 + e];
        sWh[i*PITCH + j] = g_Wh[l*4096 + e];
    }
    if (tid < 64) {
        sh_muc[tid] = g_S1c[l*64 + tid] / fmaxf(nc, 1.f);
        sh_mus[tid] = g_S1s[l*64 + tid] / fmaxf(ns, 1.f);
        sh_b[tid] = 0.f;
    }
    __syncthreads();

    const int ti = tid >> 4, tj = tid & 15;
    float acc[16];
#pragma unroll
    for (int q = 0; q < 16; q++) acc[q] = 0.f;
    mm64v(sCo, sWh, acc, ti, tj);

    float bpart[4] = {0.f,0.f,0.f,0.f};
#pragma unroll
    for (int a = 0; a < 4; a++)
#pragma unroll
        for (int b = 0; b < 4; b++) {
            int i = 4*ti + a, j = 4*tj + b;
            float tv = valid ? acc[a*4+b] : ((i == j) ? 1.f : 0.f);
            g_Tt[l*4096 + j*64 + i] = tv;     // transposed store [k][c]
            bpart[a] += acc[a*4+b] * sh_muc[j];
        }
#pragma unroll
    for (int a = 0; a < 4; a++) atomicAdd(&sh_b[4*ti + a], bpart[a]);
    __syncthreads();
    if (tid < 64) g_bv[l*64 + tid] = valid ? (sh_mus[tid] - sh_b[tid]) : 0.f;
}

// ---------------- apply: out[:,p] = T_{seg(p)} x_p + b (in-place smem, coalesced I/O) ----------------
__global__ void __launch_bounds__(256)
apply_kernel(const float* __restrict__ X,
             const int*   __restrict__ segp,
             float*       __restrict__ out)
{
    extern __shared__ float sm[];
    float* As = sm;                    // 64 * APA, column = sorted pixel position
    float* Ts = sm + 64*APA;           // 64 * TSP, Ts[k][c] = T[c][k]
    __shared__ float sh_bv[64];
    __shared__ int sh_spos[TPA];
    __shared__ int sh_hist[8], sh_off[8], sh_s[8], sh_e[8];

    const int tid = threadIdx.x;
    const int base = blockIdx.x * TPA;

    if (tid < 8) sh_hist[tid] = 0;
    __syncthreads();
    int lb = segp[base + tid];
    lb = lb < 0 ? 0 : (lb > 7 ? 7 : lb);
    atomicAdd(&sh_hist[lb], 1);
    __syncthreads();
    if (tid == 0) {
        int a = 0;
#pragma unroll
        for (int i = 0; i < 8; i++) {
            sh_s[i] = a; sh_off[i] = a;
            a += sh_hist[i];
            sh_e[i] = a;
            a = (a + 3) & ~3;               // pad next label start to quad boundary
        }
    }
    __syncthreads();
    {
        int pos = atomicAdd(&sh_off[lb], 1);
        sh_spos[tid] = pos;
    }
    __syncthreads();
    // stage features into label-sorted columns (gmem coalesced)
    for (int e = tid; e < CCH*TPA; e += 256) {
        int c = e >> 8, p = e & 255;
        As[c*APA + sh_spos[p]] = X[(size_t)c*NPIX + base + p];
    }
    __syncthreads();

    const int tc = tid & 7;        // channel group: channels [8tc, 8tc+8)
    const int tq = tid >> 3;       // quad index 0..31
    const float4* As4 = (const float4*)As;

    for (int l = 0; l < 8; l++) {
        const int s = sh_s[l], e = sh_e[l];
        if (s == e) continue;                   // uniform across block
        for (int idx = tid; idx < 4096; idx += 256)
            Ts[(idx >> 6)*TSP + (idx & 63)] = g_Tt[l*4096 + idx];
        if (tid < 64) sh_bv[tid] = g_bv[l*64 + tid];
        __syncthreads();

#pragma unroll
        for (int pass = 0; pass < 2; pass++) {
            const int p0 = s + 4*(pass*32 + tq);
            if (p0 < e) {
                float acc[8][4];
#pragma unroll
                for (int c = 0; c < 8; c++)
#pragma unroll
                    for (int u = 0; u < 4; u++) acc[c][u] = 0.f;
#pragma unroll 4
                for (int k = 0; k < 64; k++) {
                    const float4 xv = As4[k*(APA/4) + (p0 >> 2)];
                    const float4 t0 = *(const float4*)&Ts[k*TSP + 8*tc];
                    const float4 t1 = *(const float4*)&Ts[k*TSP + 8*tc + 4];
                    acc[0][0]+=t0.x*xv.x; acc[0][1]+=t0.x*xv.y; acc[0][2]+=t0.x*xv.z; acc[0][3]+=t0.x*xv.w;
                    acc[1][0]+=t0.y*xv.x; acc[1][1]+=t0.y*xv.y; acc[1][2]+=t0.y*xv.z; acc[1][3]+=t0.y*xv.w;
                    acc[2][0]+=t0.z*xv.x; acc[2][1]+=t0.z*xv.y; acc[2][2]+=t0.z*xv.z; acc[2][3]+=t0.z*xv.w;
                    acc[3][0]+=t0.w*xv.x; acc[3][1]+=t0.w*xv.y; acc[3][2]+=t0.w*xv.z; acc[3][3]+=t0.w*xv.w;
                    acc[4][0]+=t1.x*xv.x; acc[4][1]+=t1.x*xv.y; acc[4][2]+=t1.x*xv.z; acc[4][3]+=t1.x*xv.w;
                    acc[5][0]+=t1.y*xv.x; acc[5][1]+=t1.y*xv.y; acc[5][2]+=t1.y*xv.z; acc[5][3]+=t1.y*xv.w;
                    acc[6][0]+=t1.z*xv.x; acc[6][1]+=t1.z*xv.y; acc[6][2]+=t1.z*xv.z; acc[6][3]+=t1.z*xv.w;
                    acc[7][0]+=t1.w*xv.x; acc[7][1]+=t1.w*xv.y; acc[7][2]+=t1.w*xv.z; acc[7][3]+=t1.w*xv.w;
                }
                // in-place write-back: the 8 lockstep lanes sharing this quad have
                // all finished reading columns [p0, p0+4) before any store lands.
#pragma unroll
                for (int c = 0; c < 8; c++) {
                    const float bb = sh_bv[8*tc + c];
                    float4 v = make_float4(acc[c][0]+bb, acc[c][1]+bb, acc[c][2]+bb, acc[c][3]+bb);
                    *(float4*)&As[(8*tc + c)*APA + p0] = v;
                }
            }
        }
        __syncthreads();
    }

    // coalesced write-back in original pixel order
    for (int e = tid; e < CCH*TPA; e += 256) {
        int c = e >> 8, p = e & 255;
        out[(size_t)c*NPIX + base + p] = As[c*APA + sh_spos[p]];
    }
}

// ---------------- launch ----------------
extern "C" void kernel_launch(void* const* d_in, const int* in_sizes, int n_in,
                              void* d_out, int out_size)
{
    const float* Xc   = (const float*)d_in[0];
    const float* Xs   = (const float*)d_in[1];
    const int*   segc = (const int*)d_in[2];
    const int*   segs = (const int*)d_in[3];
    const int*   nlab = (n_in >= 5) ? (const int*)d_in[4] : nullptr;
    float* out = (float*)d_out;

    const int smem_stats = TP*CCH*4;                // 65536
    const int smem_ns    = 5*64*PITCH*4;            // 87040
    const int smem_comb  = 2*64*PITCH*4;            // 34816
    const int smem_apply = (64*APA + 64*TSP)*4;     // 92160

    cudaFuncSetAttribute(stats_kernel, cudaFuncAttributeMaxDynamicSharedMemorySize, smem_stats);
    cudaFuncSetAttribute(finalize_ns,  cudaFuncAttributeMaxDynamicSharedMemorySize, smem_ns);
    cudaFuncSetAttribute(apply_kernel, cudaFuncAttributeMaxDynamicSharedMemorySize, smem_apply);

    zero_kernel<<<2, 256>>>();
    stats_kernel<<<dim3(GX, 2, 2), 256, smem_stats>>>(Xc, Xs, segc, segs);
    reduce_kernel<<<256, 256>>>();
    finalize_ns<<<dim3(8, 2), 256, smem_ns>>>();
    combine_kernel<<<8, 256, smem_comb>>>(nlab);
    apply_kernel<<<NPIX/TPA, 256, smem_apply>>>(Xc, segc, out);
}